// round 3
// baseline (speedup 1.0000x reference)
#include <cuda_runtime.h>

// Problem constants (fixed by setup_inputs)
namespace {
constexpr int BTOT = 32768;
constexpr int T = 28;
constexpr int D = 28;
constexpr int H = 10;
constexpr int G = 40;      // 4*H
constexpr int HP = 12;     // H padded to multiple of 4 for float4 LDS
constexpr int BLK = 128;   // samples (threads) per CTA
constexpr int SXS = 29;    // padded x-tile row stride (conflict-free)

__device__ __forceinline__ float sigm(float x) {
    float e = __expf(-x);                       // MUFU.EX2
    return __fdividef(1.0f, 1.0f + e);          // MUFU.RCP
}
__device__ __forceinline__ float tanh_(float x) {
    float e = __expf(2.0f * x);
    return 1.0f - __fdividef(2.0f, e + 1.0f);
}

__global__ void __launch_bounds__(BLK) lstm_fused(
    const float* __restrict__ x,
    const float* __restrict__ w_ih0, const float* __restrict__ w_hh0,
    const float* __restrict__ b_ih0, const float* __restrict__ b_hh0,
    const float* __restrict__ w_ih1, const float* __restrict__ w_hh1,
    const float* __restrict__ b_ih1, const float* __restrict__ b_hh1,
    const float* __restrict__ w_cls, const float* __restrict__ b_cls,
    float* __restrict__ out)
{
    __shared__ __align__(16) float s_w0i[G * D];    // [40][28] rows 112B (16B-mult)
    __shared__ __align__(16) float s_w0h[G * HP];   // [40][12] zero-padded
    __shared__ __align__(16) float s_w1i[G * HP];
    __shared__ __align__(16) float s_w1h[G * HP];
    __shared__ __align__(16) float s_wc[10 * HP];
    __shared__ float s_b0[G];
    __shared__ float s_b1[G];
    __shared__ float s_bc[16];
    __shared__ float s_x[BLK * SXS];

    const int tid = threadIdx.x;

    // ---- stage weights into smem (once) ----
    for (int i = tid; i < G * D; i += BLK) s_w0i[i] = w_ih0[i];
    for (int i = tid; i < G * HP; i += BLK) {
        int r = i / HP, c2 = i - r * HP;
        bool v = (c2 < H);
        s_w0h[i] = v ? w_hh0[r * H + c2] : 0.0f;
        s_w1i[i] = v ? w_ih1[r * H + c2] : 0.0f;
        s_w1h[i] = v ? w_hh1[r * H + c2] : 0.0f;
    }
    for (int i = tid; i < 10 * HP; i += BLK) {
        int r = i / HP, c2 = i - r * HP;
        s_wc[i] = (c2 < H) ? w_cls[r * H + c2] : 0.0f;
    }
    if (tid < G) {
        s_b0[tid] = b_ih0[tid] + b_hh0[tid];
        s_b1[tid] = b_ih1[tid] + b_hh1[tid];
    }
    if (tid < 10) s_bc[tid] = b_cls[tid];
    __syncthreads();

    const float* xblk = x + (size_t)blockIdx.x * BLK * (T * D);

    // per-sample state (pads kept at zero so float4 recurrent FMAs are safe)
    float h0[HP], h1[HP], hn[HP], hn1[H], c0[H], c1[H];
    #pragma unroll
    for (int i = 0; i < HP; i++) { h0[i] = 0.0f; h1[i] = 0.0f; hn[i] = 0.0f; }
    #pragma unroll
    for (int i = 0; i < H; i++) { c0[i] = 0.0f; c1[i] = 0.0f; }

    // staging index decomposition: e = k*BLK + tid ; s = e/D ; d = e%D
    const int s_init = tid / D;
    const int d_init = tid - s_init * D;

    for (int t = 0; t < T; t++) {
        __syncthreads();   // previous tile fully consumed
        {
            // cooperative coalesced load of x[blk..blk+127][t][0..27]
            const float* src = xblk + t * D;
            int e = tid, s = s_init, d = d_init;
            #pragma unroll
            for (int k = 0; k < D; k++) {   // 28*128 = BLK*D elements
                s_x[e + s] = src[e + s * (T * D - D)];   // smem: s*29+d ; gmem: s*784+d
                e += BLK;
                d += (BLK - 4 * D);  // +16
                s += 4;
                if (d >= D) { d -= D; s += 1; }
            }
        }
        __syncthreads();

        float xr[D];
        #pragma unroll
        for (int dd = 0; dd < D; dd++) xr[dd] = s_x[tid * SXS + dd];

        // ---------- layer 0 ----------
        #pragma unroll
        for (int u = 0; u < H; u++) {
            float gi = s_b0[u], gf = s_b0[u + H], gg = s_b0[u + 2 * H], go = s_b0[u + 3 * H];
            const float4* wi = (const float4*)(s_w0i + u * D);
            const float4* wf = (const float4*)(s_w0i + (u + H) * D);
            const float4* wg = (const float4*)(s_w0i + (u + 2 * H) * D);
            const float4* wo = (const float4*)(s_w0i + (u + 3 * H) * D);
            #pragma unroll
            for (int q = 0; q < D / 4; q++) {
                float4 a = wi[q], b = wf[q], c = wg[q], dd = wo[q];
                gi += a.x * xr[4*q];   gi += a.y * xr[4*q+1];
                gi += a.z * xr[4*q+2]; gi += a.w * xr[4*q+3];
                gf += b.x * xr[4*q];   gf += b.y * xr[4*q+1];
                gf += b.z * xr[4*q+2]; gf += b.w * xr[4*q+3];
                gg += c.x * xr[4*q];   gg += c.y * xr[4*q+1];
                gg += c.z * xr[4*q+2]; gg += c.w * xr[4*q+3];
                go += dd.x * xr[4*q];   go += dd.y * xr[4*q+1];
                go += dd.z * xr[4*q+2]; go += dd.w * xr[4*q+3];
            }
            const float4* ri = (const float4*)(s_w0h + u * HP);
            const float4* rf = (const float4*)(s_w0h + (u + H) * HP);
            const float4* rg = (const float4*)(s_w0h + (u + 2 * H) * HP);
            const float4* ro = (const float4*)(s_w0h + (u + 3 * H) * HP);
            #pragma unroll
            for (int q = 0; q < HP / 4; q++) {
                float4 a = ri[q], b = rf[q], c = rg[q], dd = ro[q];
                gi += a.x * h0[4*q];   gi += a.y * h0[4*q+1];
                gi += a.z * h0[4*q+2]; gi += a.w * h0[4*q+3];
                gf += b.x * h0[4*q];   gf += b.y * h0[4*q+1];
                gf += b.z * h0[4*q+2]; gf += b.w * h0[4*q+3];
                gg += c.x * h0[4*q];   gg += c.y * h0[4*q+1];
                gg += c.z * h0[4*q+2]; gg += c.w * h0[4*q+3];
                go += dd.x * h0[4*q];   go += dd.y * h0[4*q+1];
                go += dd.z * h0[4*q+2]; go += dd.w * h0[4*q+3];
            }
            float ig = sigm(gi), fg = sigm(gf), gt = tanh_(gg), og = sigm(go);
            float cn = fg * c0[u] + ig * gt;
            c0[u] = cn;
            hn[u] = og * tanh_(cn);
        }

        // ---------- layer 1 (input = hn, recurrent = h1) ----------
        #pragma unroll
        for (int u = 0; u < H; u++) {
            float gi = s_b1[u], gf = s_b1[u + H], gg = s_b1[u + 2 * H], go = s_b1[u + 3 * H];
            const float4* wi = (const float4*)(s_w1i + u * HP);
            const float4* wf = (const float4*)(s_w1i + (u + H) * HP);
            const float4* wg = (const float4*)(s_w1i + (u + 2 * H) * HP);
            const float4* wo = (const float4*)(s_w1i + (u + 3 * H) * HP);
            #pragma unroll
            for (int q = 0; q < HP / 4; q++) {
                float4 a = wi[q], b = wf[q], c = wg[q], dd = wo[q];
                gi += a.x * hn[4*q];   gi += a.y * hn[4*q+1];
                gi += a.z * hn[4*q+2]; gi += a.w * hn[4*q+3];
                gf += b.x * hn[4*q];   gf += b.y * hn[4*q+1];
                gf += b.z * hn[4*q+2]; gf += b.w * hn[4*q+3];
                gg += c.x * hn[4*q];   gg += c.y * hn[4*q+1];
                gg += c.z * hn[4*q+2]; gg += c.w * hn[4*q+3];
                go += dd.x * hn[4*q];   go += dd.y * hn[4*q+1];
                go += dd.z * hn[4*q+2]; go += dd.w * hn[4*q+3];
            }
            const float4* ri = (const float4*)(s_w1h + u * HP);
            const float4* rf = (const float4*)(s_w1h + (u + H) * HP);
            const float4* rg = (const float4*)(s_w1h + (u + 2 * H) * HP);
            const float4* ro = (const float4*)(s_w1h + (u + 3 * H) * HP);
            #pragma unroll
            for (int q = 0; q < HP / 4; q++) {
                float4 a = ri[q], b = rf[q], c = rg[q], dd = ro[q];
                gi += a.x * h1[4*q];   gi += a.y * h1[4*q+1];
                gi += a.z * h1[4*q+2]; gi += a.w * h1[4*q+3];
                gf += b.x * h1[4*q];   gf += b.y * h1[4*q+1];
                gf += b.z * h1[4*q+2]; gf += b.w * h1[4*q+3];
                gg += c.x * h1[4*q];   gg += c.y * h1[4*q+1];
                gg += c.z * h1[4*q+2]; gg += c.w * h1[4*q+3];
                go += dd.x * h1[4*q];   go += dd.y * h1[4*q+1];
                go += dd.z * h1[4*q+2]; go += dd.w * h1[4*q+3];
            }
            float ig = sigm(gi), fg = sigm(gf), gt = tanh_(gg), og = sigm(go);
            float cn = fg * c1[u] + ig * gt;
            c1[u] = cn;
            hn1[u] = og * tanh_(cn);
        }

        #pragma unroll
        for (int u = 0; u < H; u++) { h0[u] = hn[u]; h1[u] = hn1[u]; }
    }

    // ---------- classifier: out[b] = h1 @ w_cls^T + b_cls ----------
    const size_t b = (size_t)blockIdx.x * BLK + tid;
    #pragma unroll
    for (int k = 0; k < 10; k++) {
        const float4* w = (const float4*)(s_wc + k * HP);
        float acc = s_bc[k];
        #pragma unroll
        for (int q = 0; q < HP / 4; q++) {
            float4 a = w[q];
            acc += a.x * h1[4*q];   acc += a.y * h1[4*q+1];
            acc += a.z * h1[4*q+2]; acc += a.w * h1[4*q+3];
        }
        out[b * 10 + k] = acc;
    }
}
} // namespace

extern "C" void kernel_launch(void* const* d_in, const int* in_sizes, int n_in,
                              void* d_out, int out_size)
{
    (void)in_sizes; (void)n_in; (void)out_size;
    const float* x     = (const float*)d_in[0];
    const float* w_ih0 = (const float*)d_in[1];
    const float* w_hh0 = (const float*)d_in[2];
    const float* b_ih0 = (const float*)d_in[3];
    const float* b_hh0 = (const float*)d_in[4];
    const float* w_ih1 = (const float*)d_in[5];
    const float* w_hh1 = (const float*)d_in[6];
    const float* b_ih1 = (const float*)d_in[7];
    const float* b_hh1 = (const float*)d_in[8];
    const float* w_cls = (const float*)d_in[9];
    const float* b_cls = (const float*)d_in[10];

    lstm_fused<<<BTOT / BLK, BLK>>>(x, w_ih0, w_hh0, b_ih0, b_hh0,
                                    w_ih1, w_hh1, b_ih1, b_hh1,
                                    w_cls, b_cls, (float*)d_out);
}